// round 7
// baseline (speedup 1.0000x reference)
#include <cuda_runtime.h>
#include <cuda_fp16.h>
#include <math.h>
#include <stdint.h>

// Problem constants
#define BB 2
#define LL 2048
#define DD 4096
#define HH 32
#define HDIM 128
#define MM (BB*LL)          // 4096 rows
#define ATT_SCALE 0.08838834764831845f

// ---------------------------------------------------------------------------
// Scratch (allocation-free rule: __device__ globals)
// ---------------------------------------------------------------------------
__device__ __half g_ah[(size_t)MM*DD];       // A hi (x or ctx)
__device__ __half g_al[(size_t)MM*DD];       // A lo
__device__ __half g_bh[(size_t)DD*DD];       // W^T fp16  [N,K]
__device__ __half g_qh[(size_t)MM*DD];       // q hi (scaled) [B,H,L,d]
__device__ __half g_ql[(size_t)MM*DD];       // q lo
__device__ __half g_kh[(size_t)MM*DD];       // k fp16
__device__ __half g_vh[(size_t)MM*DD];       // v fp16

__device__ __forceinline__ uint32_t smem_u32(const void* p) {
    uint32_t a;
    asm("{ .reg .u64 t; cvta.to.shared.u64 t, %1; cvt.u32.u64 %0, t; }"
        : "=r"(a) : "l"(p));
    return a;
}

#define LDSM4(r, addr) \
    asm volatile("ldmatrix.sync.aligned.m8n8.x4.shared.b16 {%0,%1,%2,%3}, [%4];" \
        : "=r"((r)[0]), "=r"((r)[1]), "=r"((r)[2]), "=r"((r)[3]) : "r"(addr))
#define LDSM4T(r, addr) \
    asm volatile("ldmatrix.sync.aligned.m8n8.x4.trans.shared.b16 {%0,%1,%2,%3}, [%4];" \
        : "=r"((r)[0]), "=r"((r)[1]), "=r"((r)[2]), "=r"((r)[3]) : "r"(addr))

#define MMA_F16(d, a, b0, b1) \
    asm volatile("mma.sync.aligned.m16n8k16.row.col.f32.f16.f16.f32 " \
        "{%0,%1,%2,%3}, {%4,%5,%6,%7}, {%8,%9}, {%0,%1,%2,%3};" \
        : "+f"((d)[0]), "+f"((d)[1]), "+f"((d)[2]), "+f"((d)[3]) \
        : "r"((a)[0]), "r"((a)[1]), "r"((a)[2]), "r"((a)[3]), "r"(b0), "r"(b1))

#define CP_ASYNC16(dst, src) \
    asm volatile("cp.async.cg.shared.global [%0], [%1], 16;" \
        :: "r"(dst), "l"(src) : "memory")
#define CP_COMMIT() asm volatile("cp.async.commit_group;" ::: "memory")
#define CP_WAIT1() asm volatile("cp.async.wait_group 1;" ::: "memory")
#define CP_WAIT0() asm volatile("cp.async.wait_group 0;" ::: "memory")

__device__ __forceinline__ uint32_t pack_h2(float x, float y) {
    __half2 t = __floats2half2_rn(x, y);
    return *(uint32_t*)&t;
}

// ---------------------------------------------------------------------------
// Conversion kernels
// ---------------------------------------------------------------------------
struct __align__(8) h16x4 { __half v[4]; };

__global__ __launch_bounds__(256) void conv_split_kernel(
    const float4* __restrict__ in, h16x4* __restrict__ oh, h16x4* __restrict__ ol, int n4)
{
    int i = blockIdx.x * 256 + threadIdx.x;
    if (i >= n4) return;
    float4 x = in[i];
    h16x4 h, l;
    h.v[0] = __float2half_rn(x.x); l.v[0] = __float2half_rn(x.x - __half2float(h.v[0]));
    h.v[1] = __float2half_rn(x.y); l.v[1] = __float2half_rn(x.y - __half2float(h.v[1]));
    h.v[2] = __float2half_rn(x.z); l.v[2] = __float2half_rn(x.z - __half2float(h.v[2]));
    h.v[3] = __float2half_rn(x.w); l.v[3] = __float2half_rn(x.w - __half2float(h.v[3]));
    oh[i] = h;
    ol[i] = l;
}

// W [K,N] f32 row-major -> Wt fp16 [N,K]
__global__ __launch_bounds__(256) void conv_tr_kernel(
    const float* __restrict__ W, __half* __restrict__ Th)
{
    __shared__ float sm[32][33];
    const int k0 = blockIdx.x * 32, n0 = blockIdx.y * 32;
    const int tx = threadIdx.x, ty = threadIdx.y;     // (32, 8)
#pragma unroll
    for (int i = 0; i < 4; i++)
        sm[ty + 8 * i][tx] = W[(size_t)(k0 + ty + 8 * i) * DD + n0 + tx];
    __syncthreads();
#pragma unroll
    for (int i = 0; i < 4; i++) {
        float v = sm[tx][ty + 8 * i];
        Th[(size_t)(n0 + ty + 8 * i) * DD + k0 + tx] = __float2half_rn(v);
    }
}

// ---------------------------------------------------------------------------
// HMMA GEMM: out[M,N] = A[M,K] @ W[K,N] + bias, fp16 2-term split (A hi/lo).
// CTA 128x256, 8 warps 2(m)x4(n), warp tile 64x64, K-chunk 64, 3-stage pipe.
// out_mode 0: fp32 row-major [M,N]
// out_mode 1: fp16 hi/lo split only, scaled, head-split [B,H,L,d]   (Q)
// out_mode 2: fp32 head-split + fp16 (single) head-split            (K, V)
// ---------------------------------------------------------------------------
#define KCH 64
#define ROWSTR_B 144
#define TILE_A 18432                      // 128 rows x 144 B
#define TILE_BB 36864                     // 256 rows x 144 B
#define STAGE_BYTES (2 * TILE_A + TILE_BB)   // 73728
#define GEMM_SMEM (3 * STAGE_BYTES)          // 221184
#define NCHUNK (DD / KCH)                 // 64

__global__ __launch_bounds__(256, 1) void gemm_mma_kernel(
    const __half* __restrict__ Ah, const __half* __restrict__ Al,
    const __half* __restrict__ B,
    const float* __restrict__ bias, float* __restrict__ out,
    __half* __restrict__ oh, __half* __restrict__ ol,
    float scale, int out_mode)
{
    extern __shared__ __align__(16) char smem[];
    const uint32_t sb = smem_u32(smem);
    const int tid = threadIdx.x, lane = tid & 31, wid = tid >> 5;
    const int wm = wid >> 2;              // 0..1  (64-row block)
    const int wn = wid & 3;               // 0..3  (64-col block)
    const int m0 = blockIdx.y * 128;
    const int n0 = blockIdx.x * 256;

    const __half* gA_h = Ah + (size_t)m0 * DD;
    const __half* gA_l = Al + (size_t)m0 * DD;
    const __half* gB   = B + (size_t)n0 * DD;

    float acc[4][8][4];
#pragma unroll
    for (int i = 0; i < 4; i++)
#pragma unroll
        for (int j = 0; j < 8; j++)
#pragma unroll
            for (int e = 0; e < 4; e++) acc[i][j][e] = 0.f;

    const uint32_t a_off = (uint32_t)(wm * 64 + (lane & 15)) * ROWSTR_B + ((lane >> 4) << 4);
    const uint32_t b_off = (uint32_t)(wn * 64 + ((lane >> 4) << 3) + (lane & 7)) * ROWSTR_B
                           + (((lane >> 3) & 1) << 4);

#define LOAD_CHUNK(cc, st) do {                                                \
    const uint32_t stage_ = sb + (uint32_t)(st) * STAGE_BYTES;                 \
    /* A hi/lo: 128 rows x 8 granules = 1024 each */                           \
    _Pragma("unroll")                                                          \
    for (int i_ = 0; i_ < 4; ++i_) {                                           \
        int f_ = tid + i_ * 256;                                               \
        int r_ = f_ >> 3, s_ = f_ & 7;                                         \
        size_t go_ = (size_t)r_ * DD + (size_t)(cc) * KCH + s_ * 8;            \
        uint32_t so_ = r_ * ROWSTR_B + s_ * 16;                                \
        CP_ASYNC16(stage_ + so_, gA_h + go_);                                  \
        CP_ASYNC16(stage_ + TILE_A + so_, gA_l + go_);                         \
    }                                                                          \
    /* B: 256 rows x 8 granules = 2048 */                                      \
    _Pragma("unroll")                                                          \
    for (int i_ = 0; i_ < 8; ++i_) {                                           \
        int f_ = tid + i_ * 256;                                               \
        int r_ = f_ >> 3, s_ = f_ & 7;                                         \
        CP_ASYNC16(stage_ + 2 * TILE_A + r_ * ROWSTR_B + s_ * 16,              \
                   gB + (size_t)r_ * DD + (size_t)(cc) * KCH + s_ * 8);        \
    }                                                                          \
    CP_COMMIT();                                                               \
} while (0)

    LOAD_CHUNK(0, 0);
    LOAD_CHUNK(1, 1);

#pragma unroll 1
    for (int c = 0; c < NCHUNK; ++c) {
        if (c < NCHUNK - 1) { CP_WAIT1(); } else { CP_WAIT0(); }
        __syncthreads();
        if (c + 2 < NCHUNK) LOAD_CHUNK(c + 2, (c + 2) % 3);

        const uint32_t stage = sb + (uint32_t)(c % 3) * STAGE_BYTES;
        const uint32_t a_h = stage + a_off;
        const uint32_t a_l = stage + TILE_A + a_off;
        const uint32_t b_s = stage + 2 * TILE_A + b_off;

#pragma unroll
        for (int kk = 0; kk < 4; ++kk) {
            uint32_t ah_[4][4], al_[4][4], bf_[4][4];
#pragma unroll
            for (int i = 0; i < 4; ++i) {
                LDSM4(ah_[i], a_h + i * 16 * ROWSTR_B + kk * 32);
                LDSM4(al_[i], a_l + i * 16 * ROWSTR_B + kk * 32);
            }
#pragma unroll
            for (int j = 0; j < 4; ++j)
                LDSM4(bf_[j], b_s + j * 16 * ROWSTR_B + kk * 32);
#pragma unroll
            for (int i = 0; i < 4; ++i)
#pragma unroll
                for (int jn = 0; jn < 8; ++jn)
                    MMA_F16(acc[i][jn], ah_[i], bf_[jn >> 1][(jn & 1) * 2],
                            bf_[jn >> 1][(jn & 1) * 2 + 1]);
#pragma unroll
            for (int i = 0; i < 4; ++i)
#pragma unroll
                for (int jn = 0; jn < 8; ++jn)
                    MMA_F16(acc[i][jn], al_[i], bf_[jn >> 1][(jn & 1) * 2],
                            bf_[jn >> 1][(jn & 1) * 2 + 1]);
        }
        __syncthreads();
    }
#undef LOAD_CHUNK

    // epilogue
#pragma unroll
    for (int i = 0; i < 4; ++i) {
        const int r_lo = m0 + wm * 64 + i * 16 + (lane >> 2);
#pragma unroll
        for (int jn = 0; jn < 8; ++jn) {
            const int colg = n0 + wn * 64 + jn * 8 + (lane & 3) * 2;
            const float bv0 = bias[colg], bv1 = bias[colg + 1];
#pragma unroll
            for (int half_ = 0; half_ < 2; ++half_) {
                const int row = r_lo + half_ * 8;
                float vx = acc[i][jn][half_ * 2 + 0] + bv0;
                float vy = acc[i][jn][half_ * 2 + 1] + bv1;
                if (out_mode == 0) {
                    float2 v; v.x = vx; v.y = vy;
                    *(float2*)(out + (size_t)row * DD + colg) = v;
                } else {
                    int b_ = row >> 11, l_ = row & 2047, h_ = colg >> 7, dd = colg & 127;
                    size_t idx = ((((size_t)b_ * HH + h_) * LL + l_) * HDIM) + dd;
                    if (out_mode == 2) {
                        float2 v; v.x = vx; v.y = vy;
                        *(float2*)(out + idx) = v;
                        *(uint32_t*)(oh + idx) = pack_h2(vx, vy);
                    } else {
                        float sx = vx * scale, sy = vy * scale;
                        __half hx = __float2half_rn(sx), hy = __float2half_rn(sy);
                        float rx = sx - __half2float(hx), ry = sy - __half2float(hy);
                        __half2 hp; hp.x = hx; hp.y = hy;
                        *(uint32_t*)(oh + idx) = *(uint32_t*)&hp;
                        *(uint32_t*)(ol + idx) = pack_h2(rx, ry);
                    }
                }
            }
        }
    }
}

// ---------------------------------------------------------------------------
// Flash attention (causal), HMMA fp16 2-term — unchanged from R6.
// ---------------------------------------------------------------------------
#define AROWSTR 272                       // 128 fp16 = 256 B + 16 pad
#define ATILE (64 * AROWSTR)              // 17408
#define ATT_SMEM (6 * ATILE)              // 104448: Qh, Ql, K0, V0, K1, V1

__global__ __launch_bounds__(128, 2) void attn_mma_kernel(
    const __half* __restrict__ qh, const __half* __restrict__ ql,
    const __half* __restrict__ kh, const __half* __restrict__ vh,
    __half* __restrict__ cth, __half* __restrict__ ctl)
{
    extern __shared__ __align__(16) char smem[];
    const uint32_t sb = smem_u32(smem);
    const int tid = threadIdx.x, lane = tid & 31, wid = tid >> 5;
    const int wr = wid * 16;

    const int qt = blockIdx.x, h = blockIdx.y, b = blockIdx.z;
    const int q0 = qt * 64;
    const size_t hb = ((size_t)b * HH + h) * LL * HDIM;

    {
        const __half* srcs[2] = { qh + hb, ql + hb };
#pragma unroll
        for (int t = 0; t < 2; ++t)
#pragma unroll
            for (int i = 0; i < 8; ++i) {
                int f = tid + i * 128;
                int r = f >> 4, s = f & 15;
                CP_ASYNC16(sb + t * ATILE + r * AROWSTR + s * 16,
                           srcs[t] + (size_t)(q0 + r) * HDIM + s * 8);
            }
        CP_COMMIT();
    }

#define LOAD_KV(kt_, buf_) do {                                                \
    const int k0_ = (kt_) * 64;                                                \
    const __half* srcs_[2] = { kh + hb, vh + hb };                             \
    _Pragma("unroll")                                                          \
    for (int t_ = 0; t_ < 2; ++t_)                                             \
        _Pragma("unroll")                                                      \
        for (int i_ = 0; i_ < 8; ++i_) {                                       \
            int f_ = tid + i_ * 128;                                           \
            int r_ = f_ >> 4, s_ = f_ & 15;                                    \
            CP_ASYNC16(sb + (2 + 2 * (buf_) + t_) * ATILE + r_ * AROWSTR + s_ * 16, \
                       srcs_[t_] + (size_t)(k0_ + r_) * HDIM + s_ * 8);        \
        }                                                                      \
    CP_COMMIT();                                                               \
} while (0)

    LOAD_KV(0, 0);

    float o[16][4];
#pragma unroll
    for (int i = 0; i < 16; ++i)
#pragma unroll
        for (int e = 0; e < 4; ++e) o[i][e] = 0.f;
    float m_i[2] = { -1e30f, -1e30f };
    float l_i[2] = { 0.f, 0.f };

    const uint32_t qa_off = (uint32_t)(wr + (lane & 15)) * AROWSTR + ((lane >> 4) << 4);
    const uint32_t kb_off = (uint32_t)(((lane >> 4) << 3) + (lane & 7)) * AROWSTR
                            + (((lane >> 3) & 1) << 4);
    const uint32_t vb_off = (uint32_t)(((lane >> 3) & 1) * 8 + (lane & 7)) * AROWSTR
                            + ((lane >> 4) << 4);

#pragma unroll 1
    for (int kt = 0; kt <= qt; ++kt) {
        const int k0 = kt * 64;
        __syncthreads();
        if (kt + 1 <= qt) {
            LOAD_KV(kt + 1, (kt + 1) & 1);
            CP_WAIT1();
        } else {
            CP_WAIT0();
        }
        __syncthreads();

        const uint32_t kt_s = sb + (2 + 2 * (kt & 1)) * ATILE;
        const uint32_t vt_s = sb + (3 + 2 * (kt & 1)) * ATILE;

        float s[8][4];
#pragma unroll
        for (int i = 0; i < 8; ++i)
#pragma unroll
            for (int e = 0; e < 4; ++e) s[i][e] = 0.f;

#pragma unroll
        for (int kk = 0; kk < 8; ++kk) {
            uint32_t qa_h[4], qa_l[4], kb_[4][4];
            LDSM4(qa_h, sb + 0 * ATILE + qa_off + kk * 32);
            LDSM4(qa_l, sb + 1 * ATILE + qa_off + kk * 32);
#pragma unroll
            for (int g = 0; g < 4; ++g)
                LDSM4(kb_[g], kt_s + g * 16 * AROWSTR + kb_off + kk * 32);
#pragma unroll
            for (int g = 0; g < 4; ++g)
#pragma unroll
                for (int j = 0; j < 2; ++j)
                    MMA_F16(s[2 * g + j], qa_h, kb_[g][j * 2], kb_[g][j * 2 + 1]);
#pragma unroll
            for (int g = 0; g < 4; ++g)
#pragma unroll
                for (int j = 0; j < 2; ++j)
                    MMA_F16(s[2 * g + j], qa_l, kb_[g][j * 2], kb_[g][j * 2 + 1]);
        }

        const int r0g = q0 + wr + (lane >> 2);
        if (kt == qt) {
#pragma unroll
            for (int nt = 0; nt < 8; ++nt) {
                const int cg = k0 + nt * 8 + (lane & 3) * 2;
#pragma unroll
                for (int e = 0; e < 4; ++e) {
                    const int rr = r0g + (e >> 1) * 8;
                    const int cc = cg + (e & 1);
                    if (cc > rr) s[nt][e] = -1e30f;
                }
            }
        }

        float scl[2];
#pragma unroll
        for (int rh = 0; rh < 2; ++rh) {
            float mx = -1e30f;
#pragma unroll
            for (int nt = 0; nt < 8; ++nt)
                mx = fmaxf(mx, fmaxf(s[nt][rh * 2], s[nt][rh * 2 + 1]));
            mx = fmaxf(mx, __shfl_xor_sync(0xffffffffu, mx, 1));
            mx = fmaxf(mx, __shfl_xor_sync(0xffffffffu, mx, 2));
            const float m_new = fmaxf(m_i[rh], mx);
            scl[rh] = __expf(m_i[rh] - m_new);
            float rs = 0.f;
#pragma unroll
            for (int nt = 0; nt < 8; ++nt) {
                float p0 = __expf(s[nt][rh * 2] - m_new);
                float p1 = __expf(s[nt][rh * 2 + 1] - m_new);
                s[nt][rh * 2] = p0;
                s[nt][rh * 2 + 1] = p1;
                rs += p0 + p1;
            }
            rs += __shfl_xor_sync(0xffffffffu, rs, 1);
            rs += __shfl_xor_sync(0xffffffffu, rs, 2);
            l_i[rh] = l_i[rh] * scl[rh] + rs;
            m_i[rh] = m_new;
        }
#pragma unroll
        for (int i = 0; i < 16; ++i) {
            o[i][0] *= scl[0]; o[i][1] *= scl[0];
            o[i][2] *= scl[1]; o[i][3] *= scl[1];
        }

        uint32_t pa_h[4][4], pa_l[4][4];
#pragma unroll
        for (int kk = 0; kk < 4; ++kk) {
            const int t0 = 2 * kk, t1 = 2 * kk + 1;
            const float pv[8] = { s[t0][0], s[t0][1], s[t0][2], s[t0][3],
                                  s[t1][0], s[t1][1], s[t1][2], s[t1][3] };
            float ph[8], pr[8];
#pragma unroll
            for (int e = 0; e < 8; ++e) {
                __half hh = __float2half_rn(pv[e]);
                ph[e] = __half2float(hh);
                pr[e] = pv[e] - ph[e];
            }
            pa_h[kk][0] = pack_h2(ph[0], ph[1]);
            pa_h[kk][1] = pack_h2(ph[2], ph[3]);
            pa_h[kk][2] = pack_h2(ph[4], ph[5]);
            pa_h[kk][3] = pack_h2(ph[6], ph[7]);
            pa_l[kk][0] = pack_h2(pr[0], pr[1]);
            pa_l[kk][1] = pack_h2(pr[2], pr[3]);
            pa_l[kk][2] = pack_h2(pr[4], pr[5]);
            pa_l[kk][3] = pack_h2(pr[6], pr[7]);
        }

#pragma unroll
        for (int g = 0; g < 8; ++g) {
            const int nt0 = 2 * g, nt1 = 2 * g + 1;
#pragma unroll
            for (int kk = 0; kk < 4; ++kk) {
                uint32_t vb_[4];
                LDSM4T(vb_, vt_s + (uint32_t)(kk * 16) * AROWSTR + g * 32 + vb_off);
                MMA_F16(o[nt0], pa_h[kk], vb_[0], vb_[1]);
                MMA_F16(o[nt1], pa_h[kk], vb_[2], vb_[3]);
                MMA_F16(o[nt0], pa_l[kk], vb_[0], vb_[1]);
                MMA_F16(o[nt1], pa_l[kk], vb_[2], vb_[3]);
            }
        }
    }
#undef LOAD_KV

    const float inv0 = 1.0f / l_i[0];
    const float inv1 = 1.0f / l_i[1];
    const int rg0 = b * LL + q0 + wr + (lane >> 2);
    const int rg1 = rg0 + 8;
#pragma unroll
    for (int nt = 0; nt < 16; ++nt) {
        const int col = h * HDIM + nt * 8 + (lane & 3) * 2;
        {
            float vx = o[nt][0] * inv0, vy = o[nt][1] * inv0;
            __half hx = __float2half_rn(vx), hy = __float2half_rn(vy);
            float rx = vx - __half2float(hx), ry = vy - __half2float(hy);
            __half2 hp; hp.x = hx; hp.y = hy;
            size_t idx = (size_t)rg0 * DD + col;
            *(uint32_t*)(cth + idx) = *(uint32_t*)&hp;
            *(uint32_t*)(ctl + idx) = pack_h2(rx, ry);
        }
        {
            float vx = o[nt][2] * inv1, vy = o[nt][3] * inv1;
            __half hx = __float2half_rn(vx), hy = __float2half_rn(vy);
            float rx = vx - __half2float(hx), ry = vy - __half2float(hy);
            __half2 hp; hp.x = hx; hp.y = hy;
            size_t idx = (size_t)rg1 * DD + col;
            *(uint32_t*)(cth + idx) = *(uint32_t*)&hp;
            *(uint32_t*)(ctl + idx) = pack_h2(rx, ry);
        }
    }
}

// ---------------------------------------------------------------------------
// Launch.  d_out layout: [ out (B*L*D) | k (B*H*L*d) | v (B*H*L*d) ]
// ---------------------------------------------------------------------------
extern "C" void kernel_launch(void* const* d_in, const int* in_sizes, int n_in,
                              void* d_out, int out_size)
{
    const float* x  = (const float*)d_in[0];
    const float* Wq = (const float*)d_in[2];
    const float* bq = (const float*)d_in[3];
    const float* Wk = (const float*)d_in[4];
    const float* bk = (const float*)d_in[5];
    const float* Wv = (const float*)d_in[6];
    const float* bv = (const float*)d_in[7];
    const float* Wo = (const float*)d_in[8];
    const float* bo = (const float*)d_in[9];

    float* out_p = (float*)d_out;
    float* k_out = out_p + (size_t)BB * LL * DD;
    float* v_out = k_out + (size_t)BB * HH * LL * HDIM;

    __half *ah, *al, *bh, *qh, *ql, *kh, *vh;
    cudaGetSymbolAddress((void**)&ah, g_ah);
    cudaGetSymbolAddress((void**)&al, g_al);
    cudaGetSymbolAddress((void**)&bh, g_bh);
    cudaGetSymbolAddress((void**)&qh, g_qh);
    cudaGetSymbolAddress((void**)&ql, g_ql);
    cudaGetSymbolAddress((void**)&kh, g_kh);
    cudaGetSymbolAddress((void**)&vh, g_vh);

    cudaFuncSetAttribute(gemm_mma_kernel, cudaFuncAttributeMaxDynamicSharedMemorySize, GEMM_SMEM);
    cudaFuncSetAttribute(attn_mma_kernel, cudaFuncAttributeMaxDynamicSharedMemorySize, ATT_SMEM);

    const int n4 = MM * DD / 4;
    const int cs_blocks = n4 / 256;
    dim3 tr_grid(DD / 32, DD / 32);
    dim3 tr_block(32, 8);
    dim3 gg(DD / 256, MM / 128);          // 16 x 32 = 512 CTAs

    conv_split_kernel<<<cs_blocks, 256>>>((const float4*)x, (h16x4*)ah, (h16x4*)al, n4);

    conv_tr_kernel<<<tr_grid, tr_block>>>(Wq, bh);
    gemm_mma_kernel<<<gg, 256, GEMM_SMEM>>>(ah, al, bh, bq, nullptr, qh, ql, ATT_SCALE, 1);

    conv_tr_kernel<<<tr_grid, tr_block>>>(Wk, bh);
    gemm_mma_kernel<<<gg, 256, GEMM_SMEM>>>(ah, al, bh, bk, k_out, kh, nullptr, 1.0f, 2);

    conv_tr_kernel<<<tr_grid, tr_block>>>(Wv, bh);
    gemm_mma_kernel<<<gg, 256, GEMM_SMEM>>>(ah, al, bh, bv, v_out, vh, nullptr, 1.0f, 2);

    dim3 ag(LL / 64, HH, BB);
    attn_mma_kernel<<<ag, 128, ATT_SMEM>>>(qh, ql, kh, vh, ah, al);

    conv_tr_kernel<<<tr_grid, tr_block>>>(Wo, bh);
    gemm_mma_kernel<<<gg, 256, GEMM_SMEM>>>(ah, al, bh, bo, out_p, nullptr, nullptr, 1.0f, 0);
}

// round 8
// speedup vs baseline: 1.0909x; 1.0909x over previous
#include <cuda_runtime.h>
#include <cuda_fp16.h>
#include <math.h>
#include <stdint.h>

// Problem constants
#define BB 2
#define LL 2048
#define DD 4096
#define HH 32
#define HDIM 128
#define MM (BB*LL)          // 4096 rows
#define ATT_SCALE 0.08838834764831845f

// ---------------------------------------------------------------------------
// Scratch (allocation-free rule: __device__ globals)
// ---------------------------------------------------------------------------
__device__ __half g_ah[(size_t)MM*DD];       // A hi (x or ctx)
__device__ __half g_al[(size_t)MM*DD];       // A lo
__device__ __half g_bq[(size_t)DD*DD];       // Wq^T fp16 [N,K]
__device__ __half g_bk[(size_t)DD*DD];
__device__ __half g_bv[(size_t)DD*DD];
__device__ __half g_bo[(size_t)DD*DD];
__device__ __half g_qh[(size_t)MM*DD];       // q hi (scaled) [B,H,L,d]
__device__ __half g_ql[(size_t)MM*DD];       // q lo
__device__ __half g_kh[(size_t)MM*DD];       // k fp16
__device__ __half g_vh[(size_t)MM*DD];       // v fp16

__device__ __forceinline__ uint32_t smem_u32(const void* p) {
    uint32_t a;
    asm("{ .reg .u64 t; cvta.to.shared.u64 t, %1; cvt.u32.u64 %0, t; }"
        : "=r"(a) : "l"(p));
    return a;
}

#define LDSM4(r, addr) \
    asm volatile("ldmatrix.sync.aligned.m8n8.x4.shared.b16 {%0,%1,%2,%3}, [%4];" \
        : "=r"((r)[0]), "=r"((r)[1]), "=r"((r)[2]), "=r"((r)[3]) : "r"(addr))
#define LDSM4T(r, addr) \
    asm volatile("ldmatrix.sync.aligned.m8n8.x4.trans.shared.b16 {%0,%1,%2,%3}, [%4];" \
        : "=r"((r)[0]), "=r"((r)[1]), "=r"((r)[2]), "=r"((r)[3]) : "r"(addr))

#define MMA_F16(d, a, b0, b1) \
    asm volatile("mma.sync.aligned.m16n8k16.row.col.f32.f16.f16.f32 " \
        "{%0,%1,%2,%3}, {%4,%5,%6,%7}, {%8,%9}, {%0,%1,%2,%3};" \
        : "+f"((d)[0]), "+f"((d)[1]), "+f"((d)[2]), "+f"((d)[3]) \
        : "r"((a)[0]), "r"((a)[1]), "r"((a)[2]), "r"((a)[3]), "r"(b0), "r"(b1))

#define CP_ASYNC16(dst, src) \
    asm volatile("cp.async.cg.shared.global [%0], [%1], 16;" \
        :: "r"(dst), "l"(src) : "memory")
#define CP_COMMIT() asm volatile("cp.async.commit_group;" ::: "memory")
#define CP_WAIT1() asm volatile("cp.async.wait_group 1;" ::: "memory")
#define CP_WAIT0() asm volatile("cp.async.wait_group 0;" ::: "memory")

__device__ __forceinline__ uint32_t pack_h2(float x, float y) {
    __half2 t = __floats2half2_rn(x, y);
    return *(uint32_t*)&t;
}

// ---------------------------------------------------------------------------
// Conversion kernels
// ---------------------------------------------------------------------------
struct __align__(8) h16x4 { __half v[4]; };

__global__ __launch_bounds__(256) void conv_split_kernel(
    const float4* __restrict__ in, h16x4* __restrict__ oh, h16x4* __restrict__ ol, int n4)
{
    int i = blockIdx.x * 256 + threadIdx.x;
    if (i >= n4) return;
    float4 x = in[i];
    h16x4 h, l;
    h.v[0] = __float2half_rn(x.x); l.v[0] = __float2half_rn(x.x - __half2float(h.v[0]));
    h.v[1] = __float2half_rn(x.y); l.v[1] = __float2half_rn(x.y - __half2float(h.v[1]));
    h.v[2] = __float2half_rn(x.z); l.v[2] = __float2half_rn(x.z - __half2float(h.v[2]));
    h.v[3] = __float2half_rn(x.w); l.v[3] = __float2half_rn(x.w - __half2float(h.v[3]));
    oh[i] = h;
    ol[i] = l;
}

// 4 weight transposes fused: W [K,N] f32 -> Wt fp16 [N,K], blockIdx.z picks W.
__global__ __launch_bounds__(256) void conv_tr4_kernel(
    const float* __restrict__ W0, const float* __restrict__ W1,
    const float* __restrict__ W2, const float* __restrict__ W3,
    __half* __restrict__ T0, __half* __restrict__ T1,
    __half* __restrict__ T2, __half* __restrict__ T3)
{
    const float* W = (blockIdx.z == 0) ? W0 : (blockIdx.z == 1) ? W1
                    : (blockIdx.z == 2) ? W2 : W3;
    __half* Th = (blockIdx.z == 0) ? T0 : (blockIdx.z == 1) ? T1
                : (blockIdx.z == 2) ? T2 : T3;
    __shared__ float sm[32][33];
    const int k0 = blockIdx.x * 32, n0 = blockIdx.y * 32;
    const int tx = threadIdx.x, ty = threadIdx.y;     // (32, 8)
#pragma unroll
    for (int i = 0; i < 4; i++)
        sm[ty + 8 * i][tx] = W[(size_t)(k0 + ty + 8 * i) * DD + n0 + tx];
    __syncthreads();
#pragma unroll
    for (int i = 0; i < 4; i++) {
        float v = sm[tx][ty + 8 * i];
        Th[(size_t)(n0 + ty + 8 * i) * DD + k0 + tx] = __float2half_rn(v);
    }
}

// ---------------------------------------------------------------------------
// HMMA GEMM: out[M,N] = A[M,K] @ W[K,N] + bias, fp16 2-term split (A hi/lo).
// CTA 128x128, 8 warps 2x4, warp tile 64x32, K-chunk 64.
// 2-stage pipeline, 2 CTAs/SM for cross-CTA latency hiding.
// Grid: 1D 1024, swizzled (groups of 32m x 8n) for L2 panel reuse.
// out_mode 0: fp32 row-major; 1: fp16 hi/lo scaled head-split (Q);
// 2: fp32 head-split + fp16 head-split (K,V)
// ---------------------------------------------------------------------------
#define KCH 64
#define ROWSTR_B 144
#define TILE_BYTES (128 * ROWSTR_B)       // 18432
#define STAGE_BYTES (3 * TILE_BYTES)      // 55296  (Ah, Al, B)
#define GEMM_SMEM (2 * STAGE_BYTES)       // 110592
#define NCHUNK (DD / KCH)                 // 64

__global__ __launch_bounds__(256, 2) void gemm_mma_kernel(
    const __half* __restrict__ Ah, const __half* __restrict__ Al,
    const __half* __restrict__ B,
    const float* __restrict__ bias, float* __restrict__ out,
    __half* __restrict__ oh, __half* __restrict__ ol,
    float scale, int out_mode)
{
    extern __shared__ __align__(16) char smem[];
    const uint32_t sb = smem_u32(smem);
    const int tid = threadIdx.x, lane = tid & 31, wid = tid >> 5;
    const int wm = wid >> 2;              // 0..1
    const int wn = wid & 3;               // 0..3
    // swizzled block mapping: groups of (32 m x 8 n)
    const int gid = blockIdx.x;
    const int m0 = (((gid & 255) >> 3)) * 128;
    const int n0 = (((gid >> 8) << 3) | (gid & 7)) * 128;

    const __half* gsrc[3];
    gsrc[0] = Ah + (size_t)m0 * DD;
    gsrc[1] = Al + (size_t)m0 * DD;
    gsrc[2] = B + (size_t)n0 * DD;

    float acc[4][4][4];
#pragma unroll
    for (int i = 0; i < 4; i++)
#pragma unroll
        for (int j = 0; j < 4; j++)
#pragma unroll
            for (int e = 0; e < 4; e++) acc[i][j][e] = 0.f;

    const uint32_t a_off = (uint32_t)(wm * 64 + (lane & 15)) * ROWSTR_B + ((lane >> 4) << 4);
    const uint32_t b_off = (uint32_t)(wn * 32 + ((lane >> 4) << 3) + (lane & 7)) * ROWSTR_B
                           + (((lane >> 3) & 1) << 4);

#define LOAD_CHUNK(cc, st) do {                                                \
    const uint32_t stage_ = sb + (uint32_t)(st) * STAGE_BYTES;                 \
    _Pragma("unroll")                                                          \
    for (int t_ = 0; t_ < 3; ++t_) {                                           \
        const __half* gp_ = gsrc[t_] + (size_t)(cc) * KCH;                     \
        _Pragma("unroll")                                                      \
        for (int i_ = 0; i_ < 4; ++i_) {                                       \
            int f_ = tid + i_ * 256;                                           \
            int r_ = f_ >> 3, s_ = f_ & 7;                                     \
            const void* src_ = gp_ + (size_t)r_ * DD + s_ * 8;                 \
            uint32_t dst_ = stage_ + t_ * TILE_BYTES + r_ * ROWSTR_B + s_ * 16;\
            CP_ASYNC16(dst_, src_);                                            \
        }                                                                      \
    }                                                                          \
    CP_COMMIT();                                                               \
} while (0)

    LOAD_CHUNK(0, 0);

#pragma unroll 1
    for (int c = 0; c < NCHUNK; ++c) {
        if (c + 1 < NCHUNK) {
            LOAD_CHUNK(c + 1, (c + 1) & 1);
            CP_WAIT1();
        } else {
            CP_WAIT0();
        }
        __syncthreads();

        const uint32_t stage = sb + (uint32_t)(c & 1) * STAGE_BYTES;
        const uint32_t a_h = stage + a_off;
        const uint32_t a_l = stage + TILE_BYTES + a_off;
        const uint32_t b_s = stage + 2 * TILE_BYTES + b_off;

#pragma unroll
        for (int kk = 0; kk < 4; ++kk) {
            uint32_t ah_[4][4], al_[4][4], bf_[2][4];
#pragma unroll
            for (int i = 0; i < 4; ++i) {
                LDSM4(ah_[i], a_h + i * 16 * ROWSTR_B + kk * 32);
                LDSM4(al_[i], a_l + i * 16 * ROWSTR_B + kk * 32);
            }
#pragma unroll
            for (int j = 0; j < 2; ++j)
                LDSM4(bf_[j], b_s + j * 16 * ROWSTR_B + kk * 32);
#pragma unroll
            for (int i = 0; i < 4; ++i)
#pragma unroll
                for (int jn = 0; jn < 4; ++jn)
                    MMA_F16(acc[i][jn], ah_[i], bf_[jn >> 1][(jn & 1) * 2],
                            bf_[jn >> 1][(jn & 1) * 2 + 1]);
#pragma unroll
            for (int i = 0; i < 4; ++i)
#pragma unroll
                for (int jn = 0; jn < 4; ++jn)
                    MMA_F16(acc[i][jn], al_[i], bf_[jn >> 1][(jn & 1) * 2],
                            bf_[jn >> 1][(jn & 1) * 2 + 1]);
        }
        __syncthreads();
    }
#undef LOAD_CHUNK

    // epilogue
#pragma unroll
    for (int i = 0; i < 4; ++i) {
        const int r_lo = m0 + wm * 64 + i * 16 + (lane >> 2);
#pragma unroll
        for (int jn = 0; jn < 4; ++jn) {
            const int colg = n0 + wn * 32 + jn * 8 + (lane & 3) * 2;
            const float bv0 = bias[colg], bv1 = bias[colg + 1];
#pragma unroll
            for (int half_ = 0; half_ < 2; ++half_) {
                const int row = r_lo + half_ * 8;
                float vx = acc[i][jn][half_ * 2 + 0] + bv0;
                float vy = acc[i][jn][half_ * 2 + 1] + bv1;
                if (out_mode == 0) {
                    float2 v; v.x = vx; v.y = vy;
                    *(float2*)(out + (size_t)row * DD + colg) = v;
                } else {
                    int b_ = row >> 11, l_ = row & 2047, h_ = colg >> 7, dd = colg & 127;
                    size_t idx = ((((size_t)b_ * HH + h_) * LL + l_) * HDIM) + dd;
                    if (out_mode == 2) {
                        float2 v; v.x = vx; v.y = vy;
                        *(float2*)(out + idx) = v;
                        *(uint32_t*)(oh + idx) = pack_h2(vx, vy);
                    } else {
                        float sx = vx * scale, sy = vy * scale;
                        __half hx = __float2half_rn(sx), hy = __float2half_rn(sy);
                        float rx = sx - __half2float(hx), ry = sy - __half2float(hy);
                        __half2 hp; hp.x = hx; hp.y = hy;
                        *(uint32_t*)(oh + idx) = *(uint32_t*)&hp;
                        *(uint32_t*)(ol + idx) = pack_h2(rx, ry);
                    }
                }
            }
        }
    }
}

// ---------------------------------------------------------------------------
// Flash attention (causal), HMMA fp16 2-term.
// Grid (L/128, H, B), 256 threads (8 warps x 16 q-rows = 128 q rows / CTA).
// K/V double-buffered (64-row tiles); halves K/V DRAM traffic vs 64-row CTA.
// Per-warp skip of fully-masked diagonal-right tiles.
// ---------------------------------------------------------------------------
#define AROWSTR 272                        // 128 fp16 = 256 B + 16 pad
#define ATILE_Q (128 * AROWSTR)            // 34816
#define ATILE_KV (64 * AROWSTR)            // 17408
#define ATT_SMEM (2 * ATILE_Q + 4 * ATILE_KV)   // 139264

__global__ __launch_bounds__(256, 1) void attn_mma_kernel(
    const __half* __restrict__ qh, const __half* __restrict__ ql,
    const __half* __restrict__ kh, const __half* __restrict__ vh,
    __half* __restrict__ cth, __half* __restrict__ ctl)
{
    extern __shared__ __align__(16) char smem[];
    const uint32_t sb = smem_u32(smem);
    const int tid = threadIdx.x, lane = tid & 31, wid = tid >> 5;
    const int wr = wid * 16;               // warp's q-row offset (0..112)

    const int qt = blockIdx.x, h = blockIdx.y, b = blockIdx.z;
    const int q0 = qt * 128;
    const size_t hb = ((size_t)b * HH + h) * LL * HDIM;

    // load Q tiles (hi, lo): 128 rows x 16 granules each
    {
        const __half* srcs[2] = { qh + hb, ql + hb };
#pragma unroll
        for (int t = 0; t < 2; ++t)
#pragma unroll
            for (int i = 0; i < 8; ++i) {
                int f = tid + i * 256;      // 0..2047
                int r = f >> 4, s = f & 15;
                CP_ASYNC16(sb + t * ATILE_Q + r * AROWSTR + s * 16,
                           srcs[t] + (size_t)(q0 + r) * HDIM + s * 8);
            }
        CP_COMMIT();
    }

#define LOAD_KV(kt_, buf_) do {                                                \
    const int k0_ = (kt_) * 64;                                                \
    const __half* srcs_[2] = { kh + hb, vh + hb };                             \
    _Pragma("unroll")                                                          \
    for (int t_ = 0; t_ < 2; ++t_)                                             \
        _Pragma("unroll")                                                      \
        for (int i_ = 0; i_ < 4; ++i_) {                                       \
            int f_ = tid + i_ * 256;       /* 0..1023 */                       \
            int r_ = f_ >> 4, s_ = f_ & 15;                                    \
            CP_ASYNC16(sb + 2 * ATILE_Q + (2 * (buf_) + t_) * ATILE_KV         \
                          + r_ * AROWSTR + s_ * 16,                            \
                       srcs_[t_] + (size_t)(k0_ + r_) * HDIM + s_ * 8);        \
        }                                                                      \
    CP_COMMIT();                                                               \
} while (0)

    LOAD_KV(0, 0);

    float o[16][4];
#pragma unroll
    for (int i = 0; i < 16; ++i)
#pragma unroll
        for (int e = 0; e < 4; ++e) o[i][e] = 0.f;
    float m_i[2] = { -1e30f, -1e30f };
    float l_i[2] = { 0.f, 0.f };

    const uint32_t qa_off = (uint32_t)(wr + (lane & 15)) * AROWSTR + ((lane >> 4) << 4);
    const uint32_t kb_off = (uint32_t)(((lane >> 4) << 3) + (lane & 7)) * AROWSTR
                            + (((lane >> 3) & 1) << 4);
    const uint32_t vb_off = (uint32_t)(((lane >> 3) & 1) * 8 + (lane & 7)) * AROWSTR
                            + ((lane >> 4) << 4);

    const int ktmax = 2 * qt + 1;

#pragma unroll 1
    for (int kt = 0; kt <= ktmax; ++kt) {
        const int k0 = kt * 64;
        __syncthreads();
        if (kt + 1 <= ktmax) {
            LOAD_KV(kt + 1, (kt + 1) & 1);
            CP_WAIT1();
        } else {
            CP_WAIT0();
        }
        __syncthreads();

        // per-warp skip: tile entirely above the diagonal for all 16 rows
        const bool active = (k0 <= q0 + wr + 15);
        if (active) {
            const uint32_t kt_s = sb + 2 * ATILE_Q + (2 * (kt & 1)) * ATILE_KV;
            const uint32_t vt_s = kt_s + ATILE_KV;

            float s[8][4];
#pragma unroll
            for (int i = 0; i < 8; ++i)
#pragma unroll
                for (int e = 0; e < 4; ++e) s[i][e] = 0.f;

#pragma unroll
            for (int kk = 0; kk < 8; ++kk) {
                uint32_t qa_h[4], qa_l[4], kb_[4][4];
                LDSM4(qa_h, sb + 0 * ATILE_Q + qa_off + kk * 32);
                LDSM4(qa_l, sb + 1 * ATILE_Q + qa_off + kk * 32);
#pragma unroll
                for (int g = 0; g < 4; ++g)
                    LDSM4(kb_[g], kt_s + g * 16 * AROWSTR + kb_off + kk * 32);
#pragma unroll
                for (int g = 0; g < 4; ++g)
#pragma unroll
                    for (int j = 0; j < 2; ++j)
                        MMA_F16(s[2 * g + j], qa_h, kb_[g][j * 2], kb_[g][j * 2 + 1]);
#pragma unroll
                for (int g = 0; g < 4; ++g)
#pragma unroll
                    for (int j = 0; j < 2; ++j)
                        MMA_F16(s[2 * g + j], qa_l, kb_[g][j * 2], kb_[g][j * 2 + 1]);
            }

            // mask: needed when tile isn't entirely below diag for all rows
            const int r0g = q0 + wr + (lane >> 2);
            if (k0 + 63 > q0 + wr) {
#pragma unroll
                for (int nt = 0; nt < 8; ++nt) {
                    const int cg = k0 + nt * 8 + (lane & 3) * 2;
#pragma unroll
                    for (int e = 0; e < 4; ++e) {
                        const int rr = r0g + (e >> 1) * 8;
                        const int cc = cg + (e & 1);
                        if (cc > rr) s[nt][e] = -1e30f;
                    }
                }
            }

            float scl[2];
#pragma unroll
            for (int rh = 0; rh < 2; ++rh) {
                float mx = -1e30f;
#pragma unroll
                for (int nt = 0; nt < 8; ++nt)
                    mx = fmaxf(mx, fmaxf(s[nt][rh * 2], s[nt][rh * 2 + 1]));
                mx = fmaxf(mx, __shfl_xor_sync(0xffffffffu, mx, 1));
                mx = fmaxf(mx, __shfl_xor_sync(0xffffffffu, mx, 2));
                const float m_new = fmaxf(m_i[rh], mx);
                scl[rh] = __expf(m_i[rh] - m_new);
                float rs = 0.f;
#pragma unroll
                for (int nt = 0; nt < 8; ++nt) {
                    float p0 = __expf(s[nt][rh * 2] - m_new);
                    float p1 = __expf(s[nt][rh * 2 + 1] - m_new);
                    s[nt][rh * 2] = p0;
                    s[nt][rh * 2 + 1] = p1;
                    rs += p0 + p1;
                }
                rs += __shfl_xor_sync(0xffffffffu, rs, 1);
                rs += __shfl_xor_sync(0xffffffffu, rs, 2);
                l_i[rh] = l_i[rh] * scl[rh] + rs;
                m_i[rh] = m_new;
            }
#pragma unroll
            for (int i = 0; i < 16; ++i) {
                o[i][0] *= scl[0]; o[i][1] *= scl[0];
                o[i][2] *= scl[1]; o[i][3] *= scl[1];
            }

            uint32_t pa_h[4][4], pa_l[4][4];
#pragma unroll
            for (int kk = 0; kk < 4; ++kk) {
                const int t0 = 2 * kk, t1 = 2 * kk + 1;
                const float pv[8] = { s[t0][0], s[t0][1], s[t0][2], s[t0][3],
                                      s[t1][0], s[t1][1], s[t1][2], s[t1][3] };
                float ph[8], pr[8];
#pragma unroll
                for (int e = 0; e < 8; ++e) {
                    __half hh = __float2half_rn(pv[e]);
                    ph[e] = __half2float(hh);
                    pr[e] = pv[e] - ph[e];
                }
                pa_h[kk][0] = pack_h2(ph[0], ph[1]);
                pa_h[kk][1] = pack_h2(ph[2], ph[3]);
                pa_h[kk][2] = pack_h2(ph[4], ph[5]);
                pa_h[kk][3] = pack_h2(ph[6], ph[7]);
                pa_l[kk][0] = pack_h2(pr[0], pr[1]);
                pa_l[kk][1] = pack_h2(pr[2], pr[3]);
                pa_l[kk][2] = pack_h2(pr[4], pr[5]);
                pa_l[kk][3] = pack_h2(pr[6], pr[7]);
            }

#pragma unroll
            for (int g = 0; g < 8; ++g) {
                const int nt0 = 2 * g, nt1 = 2 * g + 1;
#pragma unroll
                for (int kk = 0; kk < 4; ++kk) {
                    uint32_t vb_[4];
                    LDSM4T(vb_, vt_s + (uint32_t)(kk * 16) * AROWSTR + g * 32 + vb_off);
                    MMA_F16(o[nt0], pa_h[kk], vb_[0], vb_[1]);
                    MMA_F16(o[nt1], pa_h[kk], vb_[2], vb_[3]);
                    MMA_F16(o[nt0], pa_l[kk], vb_[0], vb_[1]);
                    MMA_F16(o[nt1], pa_l[kk], vb_[2], vb_[3]);
                }
            }
        }
    }
#undef LOAD_KV

    const float inv0 = 1.0f / l_i[0];
    const float inv1 = 1.0f / l_i[1];
    const int rg0 = b * LL + q0 + wr + (lane >> 2);
    const int rg1 = rg0 + 8;
#pragma unroll
    for (int nt = 0; nt < 16; ++nt) {
        const int col = h * HDIM + nt * 8 + (lane & 3) * 2;
        {
            float vx = o[nt][0] * inv0, vy = o[nt][1] * inv0;
            __half hx = __float2half_rn(vx), hy = __float2half_rn(vy);
            float rx = vx - __half2float(hx), ry = vy - __half2float(hy);
            __half2 hp; hp.x = hx; hp.y = hy;
            size_t idx = (size_t)rg0 * DD + col;
            *(uint32_t*)(cth + idx) = *(uint32_t*)&hp;
            *(uint32_t*)(ctl + idx) = pack_h2(rx, ry);
        }
        {
            float vx = o[nt][2] * inv1, vy = o[nt][3] * inv1;
            __half hx = __float2half_rn(vx), hy = __float2half_rn(vy);
            float rx = vx - __half2float(hx), ry = vy - __half2float(hy);
            __half2 hp; hp.x = hx; hp.y = hy;
            size_t idx = (size_t)rg1 * DD + col;
            *(uint32_t*)(cth + idx) = *(uint32_t*)&hp;
            *(uint32_t*)(ctl + idx) = pack_h2(rx, ry);
        }
    }
}

// ---------------------------------------------------------------------------
// Launch.  d_out layout: [ out (B*L*D) | k (B*H*L*d) | v (B*H*L*d) ]
// ---------------------------------------------------------------------------
extern "C" void kernel_launch(void* const* d_in, const int* in_sizes, int n_in,
                              void* d_out, int out_size)
{
    const float* x  = (const float*)d_in[0];
    const float* Wq = (const float*)d_in[2];
    const float* bq = (const float*)d_in[3];
    const float* Wk = (const float*)d_in[4];
    const float* bk = (const float*)d_in[5];
    const float* Wv = (const float*)d_in[6];
    const float* bv = (const float*)d_in[7];
    const float* Wo = (const float*)d_in[8];
    const float* bo = (const float*)d_in[9];

    float* out_p = (float*)d_out;
    float* k_out = out_p + (size_t)BB * LL * DD;
    float* v_out = k_out + (size_t)BB * HH * LL * HDIM;

    __half *ah, *al, *btq, *btk, *btv, *bto, *qh, *ql, *kh, *vh;
    cudaGetSymbolAddress((void**)&ah, g_ah);
    cudaGetSymbolAddress((void**)&al, g_al);
    cudaGetSymbolAddress((void**)&btq, g_bq);
    cudaGetSymbolAddress((void**)&btk, g_bk);
    cudaGetSymbolAddress((void**)&btv, g_bv);
    cudaGetSymbolAddress((void**)&bto, g_bo);
    cudaGetSymbolAddress((void**)&qh, g_qh);
    cudaGetSymbolAddress((void**)&ql, g_ql);
    cudaGetSymbolAddress((void**)&kh, g_kh);
    cudaGetSymbolAddress((void**)&vh, g_vh);

    cudaFuncSetAttribute(gemm_mma_kernel, cudaFuncAttributeMaxDynamicSharedMemorySize, GEMM_SMEM);
    cudaFuncSetAttribute(attn_mma_kernel, cudaFuncAttributeMaxDynamicSharedMemorySize, ATT_SMEM);

    const int n4 = MM * DD / 4;
    const int cs_blocks = n4 / 256;
    dim3 tr_grid(DD / 32, DD / 32, 4);
    dim3 tr_block(32, 8);
    const int gemm_blocks = (MM / 128) * (DD / 128);   // 1024

    // upfront conversions
    conv_split_kernel<<<cs_blocks, 256>>>((const float4*)x, (h16x4*)ah, (h16x4*)al, n4);
    conv_tr4_kernel<<<tr_grid, tr_block>>>(Wq, Wk, Wv, Wo, btq, btk, btv, bto);

    // projections
    gemm_mma_kernel<<<gemm_blocks, 256, GEMM_SMEM>>>(ah, al, btq, bq, nullptr, qh, ql, ATT_SCALE, 1);
    gemm_mma_kernel<<<gemm_blocks, 256, GEMM_SMEM>>>(ah, al, btk, bk, k_out, kh, nullptr, 1.0f, 2);
    gemm_mma_kernel<<<gemm_blocks, 256, GEMM_SMEM>>>(ah, al, btv, bv, v_out, vh, nullptr, 1.0f, 2);

    // attention -> ctx fp16 split into ah/al
    dim3 ag(LL / 128, HH, BB);
    attn_mma_kernel<<<ag, 256, ATT_SMEM>>>(qh, ql, kh, vh, ah, al);

    // output projection
    gemm_mma_kernel<<<gemm_blocks, 256, GEMM_SMEM>>>(ah, al, bto, bo, out_p, nullptr, nullptr, 1.0f, 0);
}

// round 9
// speedup vs baseline: 1.3537x; 1.2409x over previous
#include <cuda_runtime.h>
#include <cuda_fp16.h>
#include <math.h>
#include <stdint.h>

// Problem constants
#define BB 2
#define LL 2048
#define DD 4096
#define HH 32
#define HDIM 128
#define MM (BB*LL)          // 4096 rows
#define ATT_SCALE 0.08838834764831845f

// ---------------------------------------------------------------------------
// Scratch (allocation-free rule: __device__ globals)
// ---------------------------------------------------------------------------
__device__ __half g_ah[(size_t)MM*DD];       // A hi (x or ctx)
__device__ __half g_al[(size_t)MM*DD];       // A lo
__device__ __half g_bq[(size_t)DD*DD];       // Wq^T fp16 [N,K]
__device__ __half g_bk[(size_t)DD*DD];
__device__ __half g_bv[(size_t)DD*DD];
__device__ __half g_bo[(size_t)DD*DD];
__device__ __half g_qh[(size_t)MM*DD];       // q hi (scaled) [B,H,L,d]
__device__ __half g_ql[(size_t)MM*DD];       // q lo
__device__ __half g_kh[(size_t)MM*DD];       // k fp16
__device__ __half g_vh[(size_t)MM*DD];       // v fp16

__device__ __forceinline__ uint32_t smem_u32(const void* p) {
    uint32_t a;
    asm("{ .reg .u64 t; cvta.to.shared.u64 t, %1; cvt.u32.u64 %0, t; }"
        : "=r"(a) : "l"(p));
    return a;
}

#define LDSM4(r, addr) \
    asm volatile("ldmatrix.sync.aligned.m8n8.x4.shared.b16 {%0,%1,%2,%3}, [%4];" \
        : "=r"((r)[0]), "=r"((r)[1]), "=r"((r)[2]), "=r"((r)[3]) : "r"(addr))
#define LDSM4T(r, addr) \
    asm volatile("ldmatrix.sync.aligned.m8n8.x4.trans.shared.b16 {%0,%1,%2,%3}, [%4];" \
        : "=r"((r)[0]), "=r"((r)[1]), "=r"((r)[2]), "=r"((r)[3]) : "r"(addr))

#define MMA_F16(d, a, b0, b1) \
    asm volatile("mma.sync.aligned.m16n8k16.row.col.f32.f16.f16.f32 " \
        "{%0,%1,%2,%3}, {%4,%5,%6,%7}, {%8,%9}, {%0,%1,%2,%3};" \
        : "+f"((d)[0]), "+f"((d)[1]), "+f"((d)[2]), "+f"((d)[3]) \
        : "r"((a)[0]), "r"((a)[1]), "r"((a)[2]), "r"((a)[3]), "r"(b0), "r"(b1))

#define CP_ASYNC16(dst, src) \
    asm volatile("cp.async.cg.shared.global [%0], [%1], 16;" \
        :: "r"(dst), "l"(src) : "memory")
#define CP_COMMIT() asm volatile("cp.async.commit_group;" ::: "memory")
#define CP_WAIT1() asm volatile("cp.async.wait_group 1;" ::: "memory")
#define CP_WAIT0() asm volatile("cp.async.wait_group 0;" ::: "memory")

__device__ __forceinline__ uint32_t pack_h2(float x, float y) {
    __half2 t = __floats2half2_rn(x, y);
    return *(uint32_t*)&t;
}

// ---------------------------------------------------------------------------
// Conversion kernels
// ---------------------------------------------------------------------------
struct __align__(8) h16x4 { __half v[4]; };

__global__ __launch_bounds__(256) void conv_split_kernel(
    const float4* __restrict__ in, h16x4* __restrict__ oh, h16x4* __restrict__ ol, int n4)
{
    int i = blockIdx.x * 256 + threadIdx.x;
    if (i >= n4) return;
    float4 x = in[i];
    h16x4 h, l;
    h.v[0] = __float2half_rn(x.x); l.v[0] = __float2half_rn(x.x - __half2float(h.v[0]));
    h.v[1] = __float2half_rn(x.y); l.v[1] = __float2half_rn(x.y - __half2float(h.v[1]));
    h.v[2] = __float2half_rn(x.z); l.v[2] = __float2half_rn(x.z - __half2float(h.v[2]));
    h.v[3] = __float2half_rn(x.w); l.v[3] = __float2half_rn(x.w - __half2float(h.v[3]));
    oh[i] = h;
    ol[i] = l;
}

// 4 weight transposes fused: W [K,N] f32 -> Wt fp16 [N,K], blockIdx.z picks W.
__global__ __launch_bounds__(256) void conv_tr4_kernel(
    const float* __restrict__ W0, const float* __restrict__ W1,
    const float* __restrict__ W2, const float* __restrict__ W3,
    __half* __restrict__ T0, __half* __restrict__ T1,
    __half* __restrict__ T2, __half* __restrict__ T3)
{
    const float* W = (blockIdx.z == 0) ? W0 : (blockIdx.z == 1) ? W1
                    : (blockIdx.z == 2) ? W2 : W3;
    __half* Th = (blockIdx.z == 0) ? T0 : (blockIdx.z == 1) ? T1
                : (blockIdx.z == 2) ? T2 : T3;
    __shared__ float sm[32][33];
    const int k0 = blockIdx.x * 32, n0 = blockIdx.y * 32;
    const int tx = threadIdx.x, ty = threadIdx.y;     // (32, 8)
#pragma unroll
    for (int i = 0; i < 4; i++)
        sm[ty + 8 * i][tx] = W[(size_t)(k0 + ty + 8 * i) * DD + n0 + tx];
    __syncthreads();
#pragma unroll
    for (int i = 0; i < 4; i++) {
        float v = sm[tx][ty + 8 * i];
        Th[(size_t)(n0 + ty + 8 * i) * DD + k0 + tx] = __float2half_rn(v);
    }
}

// ---------------------------------------------------------------------------
// HMMA GEMM: out[M,N] = A[M,K] @ W[K,N] + bias, fp16 2-term split (A hi/lo).
// CTA 128x128, 4 warps 2x2, warp tile 64x64, K-chunk 64.
// XOR-swizzled smem (128B rows, granule g^(r&7)) -> stage 48KB, 2 stages,
// 2 CTAs/SM. Grid 1D swizzled for L2 panel reuse.
// out_mode 0: fp32 row-major; 1: fp16 hi/lo scaled head-split (Q);
// 2: fp32 head-split + fp16 head-split (K,V)
// ---------------------------------------------------------------------------
#define KCH 64
#define TILE_SZ 16384                     // 128 rows x 128 B
#define STAGE_BYTES (3 * TILE_SZ)         // 49152  (Ah, Al, B)
#define GEMM_SMEM (2 * STAGE_BYTES)       // 98304
#define NCHUNK (DD / KCH)                 // 64

__global__ __launch_bounds__(128, 2) void gemm_mma_kernel(
    const __half* __restrict__ Ah, const __half* __restrict__ Al,
    const __half* __restrict__ B,
    const float* __restrict__ bias, float* __restrict__ out,
    __half* __restrict__ oh, __half* __restrict__ ol,
    float scale, int out_mode)
{
    extern __shared__ __align__(16) char smem[];
    const uint32_t sb = smem_u32(smem);
    const int tid = threadIdx.x, lane = tid & 31, wid = tid >> 5;
    const int wm = wid >> 1;              // 0..1
    const int wn = wid & 1;               // 0..1
    // swizzled block mapping: groups of (32 m x 8 n)
    const int gid = blockIdx.x;
    const int m0 = (((gid & 255) >> 3)) * 128;
    const int n0 = (((gid >> 8) << 3) | (gid & 7)) * 128;

    const __half* gsrc[3];
    gsrc[0] = Ah + (size_t)m0 * DD;
    gsrc[1] = Al + (size_t)m0 * DD;
    gsrc[2] = B + (size_t)n0 * DD;

    float acc[4][8][4];
#pragma unroll
    for (int i = 0; i < 4; i++)
#pragma unroll
        for (int j = 0; j < 8; j++)
#pragma unroll
            for (int e = 0; e < 4; e++) acc[i][j][e] = 0.f;

    // per-lane LDSM addressing (swizzled): row stride 128B, granule ^= (row&7)
    const int rowA = wm * 64 + (lane & 15);       // +16*i
    const int a_half = lane >> 4;                 // granule half
    const int s_a = lane & 7;                     // rowA & 7
    const int rowB = wn * 64 + ((lane >> 4) << 3) + (lane & 7);   // +16*j
    const int b_half = (lane >> 3) & 1;
    const int s_b = lane & 7;                     // rowB & 7

#define LOAD_CHUNK(cc, st) do {                                                \
    const uint32_t stage_ = sb + (uint32_t)(st) * STAGE_BYTES;                 \
    _Pragma("unroll")                                                          \
    for (int t_ = 0; t_ < 3; ++t_) {                                           \
        const __half* gp_ = gsrc[t_] + (size_t)(cc) * KCH;                     \
        _Pragma("unroll")                                                      \
        for (int i_ = 0; i_ < 8; ++i_) {                                       \
            int f_ = tid + i_ * 128;              /* 0..1023 */                \
            int r_ = f_ >> 3, g_ = f_ & 7;                                     \
            const void* src_ = gp_ + (size_t)r_ * DD + g_ * 8;                 \
            uint32_t dst_ = stage_ + t_ * TILE_SZ + r_ * 128                   \
                            + ((g_ ^ (r_ & 7)) << 4);                          \
            CP_ASYNC16(dst_, src_);                                            \
        }                                                                      \
    }                                                                          \
    CP_COMMIT();                                                               \
} while (0)

    LOAD_CHUNK(0, 0);

#pragma unroll 1
    for (int c = 0; c < NCHUNK; ++c) {
        if (c + 1 < NCHUNK) {
            LOAD_CHUNK(c + 1, (c + 1) & 1);
            CP_WAIT1();
        } else {
            CP_WAIT0();
        }
        __syncthreads();

        const uint32_t stage = sb + (uint32_t)(c & 1) * STAGE_BYTES;

#pragma unroll
        for (int kk = 0; kk < 4; ++kk) {
            const uint32_t ga = (uint32_t)(((2 * kk + a_half) ^ s_a) << 4);
            const uint32_t gb = (uint32_t)(((2 * kk + b_half) ^ s_b) << 4);
            uint32_t ah_[4][4], al_[4][4], bf_[4][4];
#pragma unroll
            for (int i = 0; i < 4; ++i) {
                const uint32_t ra = (uint32_t)(rowA + i * 16) * 128 + ga;
                LDSM4(ah_[i], stage + ra);
                LDSM4(al_[i], stage + TILE_SZ + ra);
            }
#pragma unroll
            for (int j = 0; j < 4; ++j)
                LDSM4(bf_[j], stage + 2 * TILE_SZ
                              + (uint32_t)(rowB + j * 16) * 128 + gb);
#pragma unroll
            for (int i = 0; i < 4; ++i)
#pragma unroll
                for (int jn = 0; jn < 8; ++jn)
                    MMA_F16(acc[i][jn], ah_[i], bf_[jn >> 1][(jn & 1) * 2],
                            bf_[jn >> 1][(jn & 1) * 2 + 1]);
#pragma unroll
            for (int i = 0; i < 4; ++i)
#pragma unroll
                for (int jn = 0; jn < 8; ++jn)
                    MMA_F16(acc[i][jn], al_[i], bf_[jn >> 1][(jn & 1) * 2],
                            bf_[jn >> 1][(jn & 1) * 2 + 1]);
        }
        __syncthreads();
    }
#undef LOAD_CHUNK

    // epilogue
#pragma unroll
    for (int i = 0; i < 4; ++i) {
        const int r_lo = m0 + wm * 64 + i * 16 + (lane >> 2);
#pragma unroll
        for (int jn = 0; jn < 8; ++jn) {
            const int colg = n0 + wn * 64 + jn * 8 + (lane & 3) * 2;
            const float bv0 = bias[colg], bv1 = bias[colg + 1];
#pragma unroll
            for (int half_ = 0; half_ < 2; ++half_) {
                const int row = r_lo + half_ * 8;
                float vx = acc[i][jn][half_ * 2 + 0] + bv0;
                float vy = acc[i][jn][half_ * 2 + 1] + bv1;
                if (out_mode == 0) {
                    float2 v; v.x = vx; v.y = vy;
                    *(float2*)(out + (size_t)row * DD + colg) = v;
                } else {
                    int b_ = row >> 11, l_ = row & 2047, h_ = colg >> 7, dd = colg & 127;
                    size_t idx = ((((size_t)b_ * HH + h_) * LL + l_) * HDIM) + dd;
                    if (out_mode == 2) {
                        float2 v; v.x = vx; v.y = vy;
                        *(float2*)(out + idx) = v;
                        *(uint32_t*)(oh + idx) = pack_h2(vx, vy);
                    } else {
                        float sx = vx * scale, sy = vy * scale;
                        __half hx = __float2half_rn(sx), hy = __float2half_rn(sy);
                        float rx = sx - __half2float(hx), ry = sy - __half2float(hy);
                        __half2 hp; hp.x = hx; hp.y = hy;
                        *(uint32_t*)(oh + idx) = *(uint32_t*)&hp;
                        *(uint32_t*)(ol + idx) = pack_h2(rx, ry);
                    }
                }
            }
        }
    }
}

// ---------------------------------------------------------------------------
// Flash attention (causal), HMMA fp16 2-term — unchanged from R8.
// Grid (L/128, H, B), 256 threads (8 warps x 16 q-rows).
// ---------------------------------------------------------------------------
#define AROWSTR 272                        // 128 fp16 = 256 B + 16 pad
#define ATILE_Q (128 * AROWSTR)            // 34816
#define ATILE_KV (64 * AROWSTR)            // 17408
#define ATT_SMEM (2 * ATILE_Q + 4 * ATILE_KV)   // 139264

__global__ __launch_bounds__(256, 1) void attn_mma_kernel(
    const __half* __restrict__ qh, const __half* __restrict__ ql,
    const __half* __restrict__ kh, const __half* __restrict__ vh,
    __half* __restrict__ cth, __half* __restrict__ ctl)
{
    extern __shared__ __align__(16) char smem[];
    const uint32_t sb = smem_u32(smem);
    const int tid = threadIdx.x, lane = tid & 31, wid = tid >> 5;
    const int wr = wid * 16;

    const int qt = blockIdx.x, h = blockIdx.y, b = blockIdx.z;
    const int q0 = qt * 128;
    const size_t hb = ((size_t)b * HH + h) * LL * HDIM;

    {
        const __half* srcs[2] = { qh + hb, ql + hb };
#pragma unroll
        for (int t = 0; t < 2; ++t)
#pragma unroll
            for (int i = 0; i < 8; ++i) {
                int f = tid + i * 256;
                int r = f >> 4, s = f & 15;
                CP_ASYNC16(sb + t * ATILE_Q + r * AROWSTR + s * 16,
                           srcs[t] + (size_t)(q0 + r) * HDIM + s * 8);
            }
        CP_COMMIT();
    }

#define LOAD_KV(kt_, buf_) do {                                                \
    const int k0_ = (kt_) * 64;                                                \
    const __half* srcs_[2] = { kh + hb, vh + hb };                             \
    _Pragma("unroll")                                                          \
    for (int t_ = 0; t_ < 2; ++t_)                                             \
        _Pragma("unroll")                                                      \
        for (int i_ = 0; i_ < 4; ++i_) {                                       \
            int f_ = tid + i_ * 256;                                           \
            int r_ = f_ >> 4, s_ = f_ & 15;                                    \
            CP_ASYNC16(sb + 2 * ATILE_Q + (2 * (buf_) + t_) * ATILE_KV         \
                          + r_ * AROWSTR + s_ * 16,                            \
                       srcs_[t_] + (size_t)(k0_ + r_) * HDIM + s_ * 8);        \
        }                                                                      \
    CP_COMMIT();                                                               \
} while (0)

    LOAD_KV(0, 0);

    float o[16][4];
#pragma unroll
    for (int i = 0; i < 16; ++i)
#pragma unroll
        for (int e = 0; e < 4; ++e) o[i][e] = 0.f;
    float m_i[2] = { -1e30f, -1e30f };
    float l_i[2] = { 0.f, 0.f };

    const uint32_t qa_off = (uint32_t)(wr + (lane & 15)) * AROWSTR + ((lane >> 4) << 4);
    const uint32_t kb_off = (uint32_t)(((lane >> 4) << 3) + (lane & 7)) * AROWSTR
                            + (((lane >> 3) & 1) << 4);
    const uint32_t vb_off = (uint32_t)(((lane >> 3) & 1) * 8 + (lane & 7)) * AROWSTR
                            + ((lane >> 4) << 4);

    const int ktmax = 2 * qt + 1;

#pragma unroll 1
    for (int kt = 0; kt <= ktmax; ++kt) {
        const int k0 = kt * 64;
        __syncthreads();
        if (kt + 1 <= ktmax) {
            LOAD_KV(kt + 1, (kt + 1) & 1);
            CP_WAIT1();
        } else {
            CP_WAIT0();
        }
        __syncthreads();

        const bool active = (k0 <= q0 + wr + 15);
        if (active) {
            const uint32_t kt_s = sb + 2 * ATILE_Q + (2 * (kt & 1)) * ATILE_KV;
            const uint32_t vt_s = kt_s + ATILE_KV;

            float s[8][4];
#pragma unroll
            for (int i = 0; i < 8; ++i)
#pragma unroll
                for (int e = 0; e < 4; ++e) s[i][e] = 0.f;

#pragma unroll
            for (int kk = 0; kk < 8; ++kk) {
                uint32_t qa_h[4], qa_l[4], kb_[4][4];
                LDSM4(qa_h, sb + 0 * ATILE_Q + qa_off + kk * 32);
                LDSM4(qa_l, sb + 1 * ATILE_Q + qa_off + kk * 32);
#pragma unroll
                for (int g = 0; g < 4; ++g)
                    LDSM4(kb_[g], kt_s + g * 16 * AROWSTR + kb_off + kk * 32);
#pragma unroll
                for (int g = 0; g < 4; ++g)
#pragma unroll
                    for (int j = 0; j < 2; ++j)
                        MMA_F16(s[2 * g + j], qa_h, kb_[g][j * 2], kb_[g][j * 2 + 1]);
#pragma unroll
                for (int g = 0; g < 4; ++g)
#pragma unroll
                    for (int j = 0; j < 2; ++j)
                        MMA_F16(s[2 * g + j], qa_l, kb_[g][j * 2], kb_[g][j * 2 + 1]);
            }

            const int r0g = q0 + wr + (lane >> 2);
            if (k0 + 63 > q0 + wr) {
#pragma unroll
                for (int nt = 0; nt < 8; ++nt) {
                    const int cg = k0 + nt * 8 + (lane & 3) * 2;
#pragma unroll
                    for (int e = 0; e < 4; ++e) {
                        const int rr = r0g + (e >> 1) * 8;
                        const int cc = cg + (e & 1);
                        if (cc > rr) s[nt][e] = -1e30f;
                    }
                }
            }

            float scl[2];
#pragma unroll
            for (int rh = 0; rh < 2; ++rh) {
                float mx = -1e30f;
#pragma unroll
                for (int nt = 0; nt < 8; ++nt)
                    mx = fmaxf(mx, fmaxf(s[nt][rh * 2], s[nt][rh * 2 + 1]));
                mx = fmaxf(mx, __shfl_xor_sync(0xffffffffu, mx, 1));
                mx = fmaxf(mx, __shfl_xor_sync(0xffffffffu, mx, 2));
                const float m_new = fmaxf(m_i[rh], mx);
                scl[rh] = __expf(m_i[rh] - m_new);
                float rs = 0.f;
#pragma unroll
                for (int nt = 0; nt < 8; ++nt) {
                    float p0 = __expf(s[nt][rh * 2] - m_new);
                    float p1 = __expf(s[nt][rh * 2 + 1] - m_new);
                    s[nt][rh * 2] = p0;
                    s[nt][rh * 2 + 1] = p1;
                    rs += p0 + p1;
                }
                rs += __shfl_xor_sync(0xffffffffu, rs, 1);
                rs += __shfl_xor_sync(0xffffffffu, rs, 2);
                l_i[rh] = l_i[rh] * scl[rh] + rs;
                m_i[rh] = m_new;
            }
#pragma unroll
            for (int i = 0; i < 16; ++i) {
                o[i][0] *= scl[0]; o[i][1] *= scl[0];
                o[i][2] *= scl[1]; o[i][3] *= scl[1];
            }

            uint32_t pa_h[4][4], pa_l[4][4];
#pragma unroll
            for (int kk = 0; kk < 4; ++kk) {
                const int t0 = 2 * kk, t1 = 2 * kk + 1;
                const float pv[8] = { s[t0][0], s[t0][1], s[t0][2], s[t0][3],
                                      s[t1][0], s[t1][1], s[t1][2], s[t1][3] };
                float ph[8], pr[8];
#pragma unroll
                for (int e = 0; e < 8; ++e) {
                    __half hh = __float2half_rn(pv[e]);
                    ph[e] = __half2float(hh);
                    pr[e] = pv[e] - ph[e];
                }
                pa_h[kk][0] = pack_h2(ph[0], ph[1]);
                pa_h[kk][1] = pack_h2(ph[2], ph[3]);
                pa_h[kk][2] = pack_h2(ph[4], ph[5]);
                pa_h[kk][3] = pack_h2(ph[6], ph[7]);
                pa_l[kk][0] = pack_h2(pr[0], pr[1]);
                pa_l[kk][1] = pack_h2(pr[2], pr[3]);
                pa_l[kk][2] = pack_h2(pr[4], pr[5]);
                pa_l[kk][3] = pack_h2(pr[6], pr[7]);
            }

#pragma unroll
            for (int g = 0; g < 8; ++g) {
                const int nt0 = 2 * g, nt1 = 2 * g + 1;
#pragma unroll
                for (int kk = 0; kk < 4; ++kk) {
                    uint32_t vb_[4];
                    LDSM4T(vb_, vt_s + (uint32_t)(kk * 16) * AROWSTR + g * 32 + vb_off);
                    MMA_F16(o[nt0], pa_h[kk], vb_[0], vb_[1]);
                    MMA_F16(o[nt1], pa_h[kk], vb_[2], vb_[3]);
                    MMA_F16(o[nt0], pa_l[kk], vb_[0], vb_[1]);
                    MMA_F16(o[nt1], pa_l[kk], vb_[2], vb_[3]);
                }
            }
        }
    }
#undef LOAD_KV

    const float inv0 = 1.0f / l_i[0];
    const float inv1 = 1.0f / l_i[1];
    const int rg0 = b * LL + q0 + wr + (lane >> 2);
    const int rg1 = rg0 + 8;
#pragma unroll
    for (int nt = 0; nt < 16; ++nt) {
        const int col = h * HDIM + nt * 8 + (lane & 3) * 2;
        {
            float vx = o[nt][0] * inv0, vy = o[nt][1] * inv0;
            __half hx = __float2half_rn(vx), hy = __float2half_rn(vy);
            float rx = vx - __half2float(hx), ry = vy - __half2float(hy);
            __half2 hp; hp.x = hx; hp.y = hy;
            size_t idx = (size_t)rg0 * DD + col;
            *(uint32_t*)(cth + idx) = *(uint32_t*)&hp;
            *(uint32_t*)(ctl + idx) = pack_h2(rx, ry);
        }
        {
            float vx = o[nt][2] * inv1, vy = o[nt][3] * inv1;
            __half hx = __float2half_rn(vx), hy = __float2half_rn(vy);
            float rx = vx - __half2float(hx), ry = vy - __half2float(hy);
            __half2 hp; hp.x = hx; hp.y = hy;
            size_t idx = (size_t)rg1 * DD + col;
            *(uint32_t*)(cth + idx) = *(uint32_t*)&hp;
            *(uint32_t*)(ctl + idx) = pack_h2(rx, ry);
        }
    }
}

// ---------------------------------------------------------------------------
// Launch.  d_out layout: [ out (B*L*D) | k (B*H*L*d) | v (B*H*L*d) ]
// ---------------------------------------------------------------------------
extern "C" void kernel_launch(void* const* d_in, const int* in_sizes, int n_in,
                              void* d_out, int out_size)
{
    const float* x  = (const float*)d_in[0];
    const float* Wq = (const float*)d_in[2];
    const float* bq = (const float*)d_in[3];
    const float* Wk = (const float*)d_in[4];
    const float* bk = (const float*)d_in[5];
    const float* Wv = (const float*)d_in[6];
    const float* bv = (const float*)d_in[7];
    const float* Wo = (const float*)d_in[8];
    const float* bo = (const float*)d_in[9];

    float* out_p = (float*)d_out;
    float* k_out = out_p + (size_t)BB * LL * DD;
    float* v_out = k_out + (size_t)BB * HH * LL * HDIM;

    __half *ah, *al, *btq, *btk, *btv, *bto, *qh, *ql, *kh, *vh;
    cudaGetSymbolAddress((void**)&ah, g_ah);
    cudaGetSymbolAddress((void**)&al, g_al);
    cudaGetSymbolAddress((void**)&btq, g_bq);
    cudaGetSymbolAddress((void**)&btk, g_bk);
    cudaGetSymbolAddress((void**)&btv, g_bv);
    cudaGetSymbolAddress((void**)&bto, g_bo);
    cudaGetSymbolAddress((void**)&qh, g_qh);
    cudaGetSymbolAddress((void**)&ql, g_ql);
    cudaGetSymbolAddress((void**)&kh, g_kh);
    cudaGetSymbolAddress((void**)&vh, g_vh);

    cudaFuncSetAttribute(gemm_mma_kernel, cudaFuncAttributeMaxDynamicSharedMemorySize, GEMM_SMEM);
    cudaFuncSetAttribute(attn_mma_kernel, cudaFuncAttributeMaxDynamicSharedMemorySize, ATT_SMEM);

    const int n4 = MM * DD / 4;
    const int cs_blocks = n4 / 256;
    dim3 tr_grid(DD / 32, DD / 32, 4);
    dim3 tr_block(32, 8);
    const int gemm_blocks = (MM / 128) * (DD / 128);   // 1024

    // upfront conversions
    conv_split_kernel<<<cs_blocks, 256>>>((const float4*)x, (h16x4*)ah, (h16x4*)al, n4);
    conv_tr4_kernel<<<tr_grid, tr_block>>>(Wq, Wk, Wv, Wo, btq, btk, btv, bto);

    // projections
    gemm_mma_kernel<<<gemm_blocks, 128, GEMM_SMEM>>>(ah, al, btq, bq, nullptr, qh, ql, ATT_SCALE, 1);
    gemm_mma_kernel<<<gemm_blocks, 128, GEMM_SMEM>>>(ah, al, btk, bk, k_out, kh, nullptr, 1.0f, 2);
    gemm_mma_kernel<<<gemm_blocks, 128, GEMM_SMEM>>>(ah, al, btv, bv, v_out, vh, nullptr, 1.0f, 2);

    // attention -> ctx fp16 split into ah/al
    dim3 ag(LL / 128, HH, BB);
    attn_mma_kernel<<<ag, 256, ATT_SMEM>>>(qh, ql, kh, vh, ah, al);

    // output projection
    gemm_mma_kernel<<<gemm_blocks, 128, GEMM_SMEM>>>(ah, al, bto, bo, out_p, nullptr, nullptr, 1.0f, 0);
}